// round 15
// baseline (speedup 1.0000x reference)
#include <cuda_runtime.h>
#include <cuda_fp16.h>
#include <math.h>

#define HW     1024
#define TILEH  128
#define TILEW  64
#define HALO   12
#define BUFH   152
#define ROWP   104            // halves per row: data cols 0..95, pad 96..103
#define SEGS   12
#define NT     384
#define NTILES 128            // 8 row-tiles x 16 col-tiles
#define NWRD   456            // 152 rows x 3 words (96 bit-cols) for the binary path
#define INF2U  0x7C007C00u
#define TWO2U  0x40004000u

// per-tile partials: [z][img][tile][{sum_skel, sum_skel*other}]
__device__ float g_part[2*32*NTILES*2];

__device__ __forceinline__ float sigmoidf_(float x){ return 1.0f/(1.0f+__expf(-x)); }
__device__ __forceinline__ unsigned h2u(__half2 h){ return *reinterpret_cast<unsigned*>(&h); }
__device__ __forceinline__ __half2 u2h(unsigned u){ __half2 h; *reinterpret_cast<unsigned*>(&h) = u; return h; }

struct U4 { unsigned x,y,z,w; };
__device__ __forceinline__ U4 ld8h(const __half* p){
    uint4 v = *reinterpret_cast<const uint4*>(p);
    U4 r; r.x=v.x; r.y=v.y; r.z=v.z; r.w=v.w; return r;
}
__device__ __forceinline__ void st8h(__half* p, unsigned a, unsigned b, unsigned c, unsigned d){
    *reinterpret_cast<uint4*>(p) = make_uint4(a,b,c,d);
}

__device__ __forceinline__ unsigned guard_edge(const __half* p){
    __half h = *p;
    __half two = __ushort_as_half((unsigned short)0x4000u);
    __half g = __hmin(h, __hsub(two, h));
    return (unsigned)__half_as_ushort(g);
}

// guarded horizontal max3 of an 8-half row chunk
__device__ __forceinline__ U4 computeH(const __half* E, int row, int cb){
    const __half* p = E + row*ROWP + cb;
    U4 r = ld8h(p);
    unsigned gl = guard_edge(p - 1);
    unsigned gr = guard_edge(p + 8);
    __half2 two = u2h(TWO2U);
    unsigned g0 = h2u(__hmin2(u2h(r.x), __hsub2(two, u2h(r.x))));
    unsigned g1 = h2u(__hmin2(u2h(r.y), __hsub2(two, u2h(r.y))));
    unsigned g2 = h2u(__hmin2(u2h(r.z), __hsub2(two, u2h(r.z))));
    unsigned g3 = h2u(__hmin2(u2h(r.w), __hsub2(two, u2h(r.w))));
    unsigned t0 = __byte_perm(g0, gl, 0x1054);
    unsigned t1 = __byte_perm(g0, g1, 0x5432);
    unsigned t2 = __byte_perm(g1, g2, 0x5432);
    unsigned t3 = __byte_perm(g2, g3, 0x5432);
    unsigned s3 = __byte_perm(g3, gr, 0x5432);
    U4 H;
    H.x = h2u(__hmax2(u2h(t0), __hmax2(u2h(g0), u2h(t1))));
    H.y = h2u(__hmax2(u2h(t1), __hmax2(u2h(g1), u2h(t2))));
    H.z = h2u(__hmax2(u2h(t2), __hmax2(u2h(g2), u2h(t3))));
    H.w = h2u(__hmax2(u2h(t3), __hmax2(u2h(g3), u2h(s3))));
    return H;
}

// vertical max3 + relu(img - opened) accumulate (packed fp16)
__device__ __forceinline__ void outrow(const __half* IMG, int d, int cb,
                                       const U4& X, const U4& Y, const U4& Z,
                                       unsigned* sk){
    U4 im = ld8h(IMG + d*ROWP + cb);
    __half2 zero = u2h(0u);
    __half2 op, inc;
    op  = __hmax2(u2h(X.x), __hmax2(u2h(Y.x), u2h(Z.x)));
    inc = __hmax2(__hsub2(u2h(im.x), op), zero);
    sk[0] = h2u(__hadd2(u2h(sk[0]), inc));
    op  = __hmax2(u2h(X.y), __hmax2(u2h(Y.y), u2h(Z.y)));
    inc = __hmax2(__hsub2(u2h(im.y), op), zero);
    sk[1] = h2u(__hadd2(u2h(sk[1]), inc));
    op  = __hmax2(u2h(X.z), __hmax2(u2h(Y.z), u2h(Z.z)));
    inc = __hmax2(__hsub2(u2h(im.z), op), zero);
    sk[2] = h2u(__hadd2(u2h(sk[2]), inc));
    op  = __hmax2(u2h(X.w), __hmax2(u2h(Y.w), u2h(Z.w)));
    inc = __hmax2(__hsub2(u2h(im.w), op), zero);
    sk[3] = h2u(__hadd2(u2h(sk[3]), inc));
}

__global__ __launch_bounds__(NT, 2)
void cldice_main(const float* __restrict__ logits, const float* __restrict__ targets){
    extern __shared__ __half sh2[];

    const int tid  = threadIdx.x;
    const int tile = blockIdx.x;               // 0..127
    const int img  = blockIdx.y;               // 0..31
    const int z    = blockIdx.z;               // 0: skel(pred), 1: skel(gt)
    const int tr0  = (tile >> 4) * TILEH;
    const int tc0  = (tile & 15) * TILEW;
    const int base_r = tr0 - HALO;
    const size_t ioff = (size_t)img * (HW*HW);

    const int wid = tid >> 5;
    float acc0 = 0.f, acc1 = 0.f;

    if (z == 1){
        // ================= binary bit-plane path (targets are 0/1) =================
        unsigned* bP = reinterpret_cast<unsigned*>(sh2);
        unsigned* bQ = bP + NWRD;
        unsigned* bV = bQ + NWRD;
        const float* tgt = targets + ioff;

        // in-image column masks for the 3 words (buffer col c <-> image col tc0+c-16)
        unsigned colm[3];
        #pragma unroll
        for (int w = 0; w < 3; w++){
            int lo = 16 - tc0 - 32*w;       if (lo < 0) lo = 0;
            int hi = HW + 16 - tc0 - 32*w;  if (hi > 32) hi = 32;
            unsigned m = 0u;
            if (hi > lo){
                unsigned mh = (hi == 32) ? 0xFFFFFFFFu : ((1u << hi) - 1u);
                unsigned ml = (lo == 0)  ? 0u           : ((1u << lo) - 1u);
                m = mh & ~ml;
            }
            colm[w] = m;
        }

        // ---- load field bits (out-of-image = 0) ----
        for (int i = tid; i < NWRD; i += NT){
            int r = i / 3, w = i - 3*r;
            int gr = base_r + r;
            unsigned word = 0u;
            if ((unsigned)gr < (unsigned)HW){
                const float* rp = tgt + (size_t)gr*HW;
                int icb = tc0 + 32*w - 16;
                if (icb >= 0 && icb + 31 < HW){
                    #pragma unroll
                    for (int q = 0; q < 8; q++){
                        float4 v = *reinterpret_cast<const float4*>(rp + icb + 4*q);
                        unsigned b = (v.x!=0.f?1u:0u) | (v.y!=0.f?2u:0u)
                                   | (v.z!=0.f?4u:0u) | (v.w!=0.f?8u:0u);
                        word |= b << (4*q);
                    }
                } else {
                    for (int b = 0; b < 32; b++){
                        int ic = icb + b;
                        if ((unsigned)ic < (unsigned)HW && rp[ic] != 0.f) word |= 1u << b;
                    }
                }
            }
            bP[i] = word;
        }
        __syncthreads();

        // per-owned-word 4-bit skel counters (bit planes)
        unsigned c0[2]={0,0}, c1[2]={0,0}, c2[2]={0,0}, c3[2]={0,0};
        unsigned* P = bP;
        unsigned* Q = bQ;

        #pragma unroll 1
        for (int t = 0; t < 10; t++){
            unsigned orv = 0u;
            // erode rows 1..150 (AND of 5-neighborhood; out-of-image/buffer = identity 1)
            for (int i = tid; i < NWRD; i += NT){
                int r = i / 3, w = i - 3*r;
                orv |= P[i];
                if (r >= 1 && r <= 150){
                    int gr = base_r + r;
                    bool rok = (unsigned)gr < (unsigned)HW;
                    unsigned inm = rok ? colm[w] : 0u;
                    unsigned C = P[i] | ~inm;
                    unsigned Uv, Dv;
                    if (r == 1 && t > 0) Uv = 0xFFFFFFFFu;   // row0 stale after t=0; outputs unneeded
                    else {
                        unsigned inmu = ((unsigned)(gr-1) < (unsigned)HW) ? colm[w] : 0u;
                        Uv = P[i-3] | ~inmu;
                    }
                    if (r == 150 && t > 0) Dv = 0xFFFFFFFFu;
                    else {
                        unsigned inmd = ((unsigned)(gr+1) < (unsigned)HW) ? colm[w] : 0u;
                        Dv = P[i+3] | ~inmd;
                    }
                    unsigned CL = (w > 0) ? (P[i-1] | ~(rok ? colm[w-1] : 0u)) : 0xFFFFFFFFu;
                    unsigned CR = (w < 2) ? (P[i+1] | ~(rok ? colm[w+1] : 0u)) : 0xFFFFFFFFu;
                    unsigned Lv = (C << 1) | (CL >> 31);
                    unsigned Rv = (C >> 1) | (CR << 31);
                    Q[i] = C & Uv & Dv & Lv & Rv & inm;
                }
            }
            if (__syncthreads_or((int)(orv != 0u)) == 0) break;

            // vertical OR of eroded rows (rows 11..140)
            for (int i = tid; i < NWRD; i += NT){
                int r = i / 3;
                if (r >= 11 && r <= 140)
                    bV[i] = Q[i-3] | Q[i] | Q[i+3];
            }
            __syncthreads();

            // open (horizontal OR) + increment into bit-plane counters (tile rows 12..139)
            {
                int slot = 0;
                for (int i = tid; i < NWRD; i += NT, slot++){
                    int r = i / 3, w = i - 3*r;
                    if (r >= 12 && r <= 139){
                        unsigned Vc = bV[i];
                        unsigned VL = (w > 0) ? bV[i-1] : 0u;
                        unsigned VR = (w < 2) ? bV[i+1] : 0u;
                        unsigned op = Vc | ((Vc << 1) | (VL >> 31)) | ((Vc >> 1) | (VR << 31));
                        unsigned tm = (w == 0) ? 0xFFFF0000u : (w == 2 ? 0x0000FFFFu : 0xFFFFFFFFu);
                        unsigned inc = P[i] & ~op & tm;
                        unsigned cy0 = inc & c0[slot];  c0[slot] ^= inc;
                        unsigned cy1 = cy0 & c1[slot];  c1[slot] ^= cy0;
                        unsigned cy2 = cy1 & c2[slot];  c2[slot] ^= cy1;
                        c3[slot] ^= cy2;                 // skel <= 10 fits in 4 bits
                    }
                }
            }
            __syncthreads();
            unsigned* tmpp = P; P = Q; Q = tmpp;
        }

        // ---- accumulate: acc0 = sum skel, acc1 = sum skel * sigmoid(logits) ----
        {
            const float* lg = logits + ioff;
            int slot = 0;
            for (int i = tid; i < NWRD; i += NT, slot++){
                unsigned p0=c0[slot], p1=c1[slot], p2=c2[slot], p3=c3[slot];
                unsigned bits = p0 | p1 | p2 | p3;
                if (bits){
                    acc0 += (float)(__popc(p0) + 2*__popc(p1) + 4*__popc(p2) + 8*__popc(p3));
                    int r = i / 3, w = i - 3*r;
                    const float* rp = lg + (size_t)(base_r + r)*HW;
                    int icb = tc0 + 32*w - 16;
                    do {
                        int b = __ffs((int)bits) - 1;
                        float skel = (float)(((p0>>b)&1u) + 2u*((p1>>b)&1u)
                                           + 4u*((p2>>b)&1u) + 8u*((p3>>b)&1u));
                        acc1 += skel * sigmoidf_(rp[icb + b]);
                        bits &= bits - 1u;
                    } while (bits);
                }
            }
        }
        __syncthreads();   // done reading bit buffers before reduction reuses sh2
    } else {
        // ================= fp16 path (sigmoid(logits) field) =================
        __half* W0 = sh2;
        __half* W1 = sh2 +   BUFH*ROWP;
        __half* W2 = sh2 + 2*BUFH*ROWP;
        const float* src = logits + ioff;

        const bool interior = (base_r >= 0) && (base_r + BUFH <= HW)
                           && (tc0 >= 16) && (tc0 + 95 - 16 < HW);

        for (int i = tid; i < BUFH*SEGS; i += NT){
            int r = i / SEGS, s = i - r*SEGS;
            int gr = base_r + r;
            int icb = tc0 + 8*s - 16;
            unsigned o0,o1,o2,o3;
            bool rok = (unsigned)gr < (unsigned)HW;
            if (rok && icb >= 0 && icb + 7 < HW){
                const float4* rp = reinterpret_cast<const float4*>(src + (size_t)gr*HW + icb);
                float4 a = rp[0], b4 = rp[1];
                a.x=sigmoidf_(a.x); a.y=sigmoidf_(a.y); a.z=sigmoidf_(a.z); a.w=sigmoidf_(a.w);
                b4.x=sigmoidf_(b4.x); b4.y=sigmoidf_(b4.y); b4.z=sigmoidf_(b4.z); b4.w=sigmoidf_(b4.w);
                o0 = h2u(__floats2half2_rn(a.x,a.y));
                o1 = h2u(__floats2half2_rn(a.z,a.w));
                o2 = h2u(__floats2half2_rn(b4.x,b4.y));
                o3 = h2u(__floats2half2_rn(b4.z,b4.w));
            } else {
                unsigned short hh[8];
                #pragma unroll
                for (int k = 0; k < 8; k++){
                    int ic = icb + k;
                    if (rok && (unsigned)ic < (unsigned)HW){
                        hh[k] = __half_as_ushort(__float2half_rn(sigmoidf_(src[(size_t)gr*HW + ic])));
                    } else hh[k] = (unsigned short)0x7C00u;
                }
                o0 = (unsigned)hh[0] | ((unsigned)hh[1]<<16);
                o1 = (unsigned)hh[2] | ((unsigned)hh[3]<<16);
                o2 = (unsigned)hh[4] | ((unsigned)hh[5]<<16);
                o3 = (unsigned)hh[6] | ((unsigned)hh[7]<<16);
            }
            st8h(W0 + r*ROWP + 8*s, o0,o1,o2,o3);
        }
        for (int r = tid; r < BUFH; r += NT){
            st8h(W0 + r*ROWP + 96, INF2U,INF2U,INF2U,INF2U);
            st8h(W1 + r*ROWP + 96, INF2U,INF2U,INF2U,INF2U);
            st8h(W2 + r*ROWP + 96, INF2U,INF2U,INF2U,INF2U);
        }
        __syncthreads();

        const int eseg = tid % SEGS;
        const int eg   = tid / SEGS;
        int er0, ecnt;
        if (eg < 22){ er0 = 1 + 5*eg;          ecnt = 5; }
        else        { er0 = 111 + 4*(eg-22);   ecnt = 4; }
        const bool segmid = (eseg >= 1 && eseg <= 10);
        unsigned cm[4];
        {
            int icb = tc0 + 8*eseg - 16;
            #pragma unroll
            for (int m = 0; m < 4; m++){
                int i0 = icb + 2*m;
                unsigned lo = ((unsigned)i0     < (unsigned)HW) ? 0x0000FFFFu : 0u;
                unsigned hi = ((unsigned)(i0+1) < (unsigned)HW) ? 0xFFFF0000u : 0u;
                cm[m] = lo | hi;
            }
        }

        const int sd = tid & 7;
        const int gd = tid >> 3;
        const bool dact = (tid < 256);
        const int d0 = HALO + 4*gd;
        const int cb = 16 + 8*sd;

        unsigned sk[16];
        #pragma unroll
        for (int i = 0; i < 16; i++) sk[i] = 0u;

        __half* IMG = W0;
        __half* E   = W1;
        __half* C   = W2;

        #pragma unroll 1
        for (int t = 0; t < 10; t++){
            unsigned orv = 0u;
            const int r_lo = 2 + t, r_hi = 149 - t;
            if (segmid || t <= 1){
                int k0 = r_lo - er0; if (k0 < 0) k0 = 0;
                int k1 = r_hi - er0; if (k1 > ecnt-1) k1 = ecnt-1;
                if (k0 <= k1){
                    const __half* rowc = IMG + (er0+k0)*ROWP + 8*eseg;
                    __half*       erow = E   + (er0+k0)*ROWP + 8*eseg;
                    U4 up  = ld8h(rowc - ROWP);
                    U4 cur = ld8h(rowc);
                    if (interior){
                        #pragma unroll 1
                        for (int k = k0; k <= k1; k++){
                            U4 dn = ld8h(rowc + ROWP);
                            unsigned lh = (unsigned)__half_as_ushort(rowc[-1]);
                            unsigned rh = (unsigned)__half_as_ushort(rowc[8]);
                            orv |= (cur.x | cur.y) | (cur.z | cur.w);
                            __half2 v0 = __hmin2(u2h(up.x), u2h(dn.x));
                            __half2 v1 = __hmin2(u2h(up.y), u2h(dn.y));
                            __half2 v2 = __hmin2(u2h(up.z), u2h(dn.z));
                            __half2 v3 = __hmin2(u2h(up.w), u2h(dn.w));
                            unsigned t0 = __byte_perm(cur.x, lh,    0x1054);
                            unsigned t1 = __byte_perm(cur.x, cur.y, 0x5432);
                            unsigned t2 = __byte_perm(cur.y, cur.z, 0x5432);
                            unsigned t3 = __byte_perm(cur.z, cur.w, 0x5432);
                            unsigned s3 = __byte_perm(cur.w, rh,    0x5432);
                            __half2 h0 = __hmin2(u2h(t0), u2h(t1));
                            __half2 h1 = __hmin2(u2h(t1), u2h(t2));
                            __half2 h2 = __hmin2(u2h(t2), u2h(t3));
                            __half2 h3 = __hmin2(u2h(t3), u2h(s3));
                            unsigned e0 = h2u(__hmin2(u2h(cur.x), __hmin2(v0, h0)));
                            unsigned e1 = h2u(__hmin2(u2h(cur.y), __hmin2(v1, h1)));
                            unsigned e2 = h2u(__hmin2(u2h(cur.z), __hmin2(v2, h2)));
                            unsigned e3 = h2u(__hmin2(u2h(cur.w), __hmin2(v3, h3)));
                            st8h(erow, e0,e1,e2,e3);
                            up = cur; cur = dn;
                            rowc += ROWP; erow += ROWP;
                        }
                    } else {
                        #pragma unroll 1
                        for (int k = k0; k <= k1; k++){
                            U4 dn = ld8h(rowc + ROWP);
                            unsigned lh = (unsigned)__half_as_ushort(rowc[-1]);
                            unsigned rh = (unsigned)__half_as_ushort(rowc[8]);
                            __half2 v0 = __hmin2(u2h(up.x), u2h(dn.x));
                            __half2 v1 = __hmin2(u2h(up.y), u2h(dn.y));
                            __half2 v2 = __hmin2(u2h(up.z), u2h(dn.z));
                            __half2 v3 = __hmin2(u2h(up.w), u2h(dn.w));
                            unsigned t0 = __byte_perm(cur.x, lh,    0x1054);
                            unsigned t1 = __byte_perm(cur.x, cur.y, 0x5432);
                            unsigned t2 = __byte_perm(cur.y, cur.z, 0x5432);
                            unsigned t3 = __byte_perm(cur.z, cur.w, 0x5432);
                            unsigned s3 = __byte_perm(cur.w, rh,    0x5432);
                            __half2 h0 = __hmin2(u2h(t0), u2h(t1));
                            __half2 h1 = __hmin2(u2h(t1), u2h(t2));
                            __half2 h2 = __hmin2(u2h(t2), u2h(t3));
                            __half2 h3 = __hmin2(u2h(t3), u2h(s3));
                            unsigned e0 = h2u(__hmin2(u2h(cur.x), __hmin2(v0, h0)));
                            unsigned e1 = h2u(__hmin2(u2h(cur.y), __hmin2(v1, h1)));
                            unsigned e2 = h2u(__hmin2(u2h(cur.z), __hmin2(v2, h2)));
                            unsigned e3 = h2u(__hmin2(u2h(cur.w), __hmin2(v3, h3)));
                            const bool rok = (unsigned)(base_r + er0 + k) < (unsigned)HW;
                            unsigned cc0 = rok ? cm[0] : 0u;
                            unsigned cc1 = rok ? cm[1] : 0u;
                            unsigned cc2 = rok ? cm[2] : 0u;
                            unsigned cc3 = rok ? cm[3] : 0u;
                            orv |= (cur.x & cc0) | (cur.y & cc1) | (cur.z & cc2) | (cur.w & cc3);
                            e0 = (e0 & cc0) | (INF2U & ~cc0);
                            e1 = (e1 & cc1) | (INF2U & ~cc1);
                            e2 = (e2 & cc2) | (INF2U & ~cc2);
                            e3 = (e3 & cc3) | (INF2U & ~cc3);
                            st8h(erow, e0,e1,e2,e3);
                            up = cur; cur = dn;
                            rowc += ROWP; erow += ROWP;
                        }
                    }
                }
            }
            if (__syncthreads_or((int)(orv != 0u)) == 0) break;

            if (dact){
                U4 h0 = computeH(E, d0-1, cb);
                U4 h1 = computeH(E, d0,   cb);
                U4 h2 = computeH(E, d0+1, cb);
                outrow(IMG, d0,   cb, h0, h1, h2, sk);
                h0 = computeH(E, d0+2, cb);
                outrow(IMG, d0+1, cb, h1, h2, h0, sk+4);
                h1 = computeH(E, d0+3, cb);
                outrow(IMG, d0+2, cb, h2, h0, h1, sk+8);
                h2 = computeH(E, d0+4, cb);
                outrow(IMG, d0+3, cb, h0, h1, h2, sk+12);
            }

            __half* tmp = IMG;
            IMG = E; E = C; C = tmp;
        }
        __syncthreads();

        if (dact){
            const float* oth = targets + ioff;
            const int gr0 = tr0 + 4*gd;
            const int gc  = tc0 + 8*sd;
            #pragma unroll
            for (int j = 0; j < 4; j++){
                const float4* rp = reinterpret_cast<const float4*>(oth + (size_t)(gr0+j)*HW + gc);
                float4 oA = rp[0], oB = rp[1];
                float2 f0 = __half22float2(u2h(sk[4*j+0]));
                float2 f1 = __half22float2(u2h(sk[4*j+1]));
                float2 f2 = __half22float2(u2h(sk[4*j+2]));
                float2 f3 = __half22float2(u2h(sk[4*j+3]));
                acc0 += (f0.x+f0.y) + (f1.x+f1.y) + (f2.x+f2.y) + (f3.x+f3.y);
                acc1 += f0.x*oA.x + f0.y*oA.y + f1.x*oA.z + f1.y*oA.w
                      + f2.x*oB.x + f2.y*oB.y + f3.x*oB.z + f3.y*oB.w;
            }
        }
    }

    // ---- shared reduction into g_part ----
    #pragma unroll
    for (int off = 16; off; off >>= 1){
        acc0 += __shfl_xor_sync(0xffffffffu, acc0, off);
        acc1 += __shfl_xor_sync(0xffffffffu, acc1, off);
    }
    float* red = reinterpret_cast<float*>(sh2);
    if ((tid & 31) == 0){ red[wid*2] = acc0; red[wid*2+1] = acc1; }
    __syncthreads();
    if (tid < 16){
        float a0 = (tid < 12) ? red[tid*2]   : 0.f;
        float a1 = (tid < 12) ? red[tid*2+1] : 0.f;
        #pragma unroll
        for (int off = 8; off; off >>= 1){
            a0 += __shfl_xor_sync(0x0000ffffu, a0, off, 16);
            a1 += __shfl_xor_sync(0x0000ffffu, a1, off, 16);
        }
        if (tid == 0){
            const int base = ((z*32 + img)*NTILES + tile)*2;
            g_part[base + 0] = a0;
            g_part[base + 1] = a1;
        }
    }
}

__global__ void cldice_finalize(float* __restrict__ out){
    const int tid  = threadIdx.x;
    const int im   = tid >> 5;
    const int lane = tid & 31;
    __shared__ float sh[32];
    float S2 = 0.f, S1 = 0.f, S4 = 0.f, S3 = 0.f;
    for (int t = lane; t < NTILES; t += 32){
        const int b0 = ((0*32 + im)*NTILES + t)*2;
        const int b1 = ((1*32 + im)*NTILES + t)*2;
        S2 += g_part[b0 + 0];
        S1 += g_part[b0 + 1];
        S4 += g_part[b1 + 0];
        S3 += g_part[b1 + 1];
    }
    #pragma unroll
    for (int off = 16; off; off >>= 1){
        S2 += __shfl_xor_sync(0xffffffffu, S2, off);
        S1 += __shfl_xor_sync(0xffffffffu, S1, off);
        S4 += __shfl_xor_sync(0xffffffffu, S4, off);
        S3 += __shfl_xor_sync(0xffffffffu, S3, off);
    }
    if (lane == 0){
        const float eps = 1e-6f;
        const float tp = S1 / (S2 + eps);
        const float ts = S3 / (S4 + eps);
        sh[im] = 2.0f*tp*ts / (tp + ts + eps);
    }
    __syncthreads();
    if (tid < 32){
        float c = sh[tid];
        #pragma unroll
        for (int off = 16; off; off >>= 1)
            c += __shfl_xor_sync(0xffffffffu, c, off);
        if (tid == 0)
            out[0] = 1.0f - c * (1.0f/32.0f);
    }
}

extern "C" void kernel_launch(void* const* d_in, const int* in_sizes, int n_in,
                              void* d_out, int out_size){
    const float* logits  = (const float*)d_in[0];
    const float* targets = (const float*)d_in[1];
    float* out = (float*)d_out;

    const int smem = 3*BUFH*ROWP*(int)sizeof(__half);
    cudaFuncSetAttribute(cldice_main, cudaFuncAttributeMaxDynamicSharedMemorySize, smem);

    dim3 grid(NTILES, 32, 2);
    cldice_main<<<grid, NT, smem>>>(logits, targets);
    cldice_finalize<<<1, 1024>>>(out);
}